// round 16
// baseline (speedup 1.0000x reference)
#include <cuda_runtime.h>
#include <math.h>

// Problem constants
#define Lc 2048
#define Hc 8
#define Bc 8
#define Sc 128
#define HSc 1024

// ---------------- scratch (device globals) ----------------------------------
__device__ float d_eT[Hc * Lc];       // eT[h][d] = exp(W[d][h])
__device__ float d_zinv[Lc * Hc];     // 1/Z[l][h]
__device__ float d_q[Bc * HSc];
__device__ float d_u[Bc * HSc];
__device__ float d_G[Hc * Lc * Bc];   // G2[h][j][b] (accumulated, zeroed in init)
__device__ float d_scores[Bc * Lc];

// f32x2 packed helpers (sm_100+)
__device__ __forceinline__ unsigned long long pack2(float v) {
    unsigned long long r;
    asm("mov.b64 %0, {%1, %1};" : "=l"(r) : "f"(v));
    return r;
}
__device__ __forceinline__ void fma2(unsigned long long& acc,
                                     unsigned long long a, unsigned long long b) {
    asm("fma.rn.f32x2 %0, %1, %2, %0;" : "+l"(acc) : "l"(a), "l"(b));
}
__device__ __forceinline__ float2 unpack2(unsigned long long v) {
    float2 r;
    asm("mov.b64 {%0, %1}, %2;" : "=f"(r.x), "=f"(r.y) : "l"(v));
    return r;
}

// ---------------- K0: init = scan (blocks 0..7) + zero (blocks 8..23) ------
__global__ void __launch_bounds__(1024) k_init(const float* __restrict__ W,
                                               float* __restrict__ out) {
    int blk = blockIdx.x;
    int t = threadIdx.x;
    if (blk < 8) {
        int h = blk;
        float v0 = expf(W[(2 * t) * Hc + h]);
        float v1 = expf(W[(2 * t + 1) * Hc + h]);
        float s = v0 + v1;
        unsigned lane = t & 31, wid = t >> 5;
        float x = s;
        #pragma unroll
        for (int o = 1; o < 32; o <<= 1) {
            float y = __shfl_up_sync(0xffffffffu, x, o);
            if (lane >= (unsigned)o) x += y;
        }
        __shared__ float wsum[32];
        if (lane == 31) wsum[wid] = x;
        __syncthreads();
        if (wid == 0) {
            float ws = wsum[lane];
            #pragma unroll
            for (int o = 1; o < 32; o <<= 1) {
                float y = __shfl_up_sync(0xffffffffu, ws, o);
                if (lane >= (unsigned)o) ws += y;
            }
            wsum[lane] = ws;
        }
        __syncthreads();
        float warp_off = (wid == 0) ? 0.f : wsum[wid - 1];
        float incl = x + warp_off;
        float excl = incl - s;
        d_eT[h * Lc + 2 * t]     = v0;
        d_eT[h * Lc + 2 * t + 1] = v1;
        d_zinv[(2 * t) * Hc + h]     = 1.f / (excl + v0);
        d_zinv[(2 * t + 1) * Hc + h] = 1.f / incl;
    } else {
        int i = (blk - 8) * 1024 + t;
        if (i < Bc * HSc) { d_q[i] = 0.f; d_u[i] = 0.f; }
        if (i < Bc * Lc)  d_scores[i] = 0.f;
        if (i < Bc * Sc)  out[i] = 0.f;
        // zero d_G: 131072 floats = 16384 indices x 8
        float4 z4 = make_float4(0.f, 0.f, 0.f, 0.f);
        *(float4*)&d_G[i * 8]     = z4;
        *(float4*)&d_G[i * 8 + 4] = z4;
    }
}

// ---------------- K1: q_raw[b][h*S+s] = sum_j e[L-1-j,h] * x[b,j,s] --------
// grid (L/32, B) = 512 blocks, block 128 (thread = s). Batch-32 loads.
__global__ void __launch_bounds__(128) k_q(const float* __restrict__ x) {
    int jbase = blockIdx.x * 32;
    int b = blockIdx.y;
    int s = threadIdx.x;
    __shared__ __align__(16) float se[32 * 8];   // se[jj][h]
    for (int i = s; i < 32 * 8; i += 128) {
        int jj = i >> 3, h = i & 7;
        se[i] = d_eT[h * Lc + (Lc - 1 - (jbase + jj))];
    }
    __syncthreads();

    unsigned long long a2[4] = {};
    const float* xp = x + ((size_t)b * Lc + jbase) * Sc + s;
    float xv[32];
    #pragma unroll
    for (int k = 0; k < 32; k++) xv[k] = xp[k * Sc];
    #pragma unroll
    for (int k = 0; k < 32; k++) {
        unsigned long long xd = pack2(xv[k]);
        ulonglong2 e01 = *(const ulonglong2*)&se[k * 8];
        ulonglong2 e23 = *(const ulonglong2*)&se[k * 8 + 4];
        fma2(a2[0], xd, e01.x);
        fma2(a2[1], xd, e01.y);
        fma2(a2[2], xd, e23.x);
        fma2(a2[3], xd, e23.y);
    }
    #pragma unroll
    for (int p = 0; p < 4; p++) {
        float2 v = unpack2(a2[p]);
        atomicAdd(&d_q[b * HSc + (2 * p) * Sc + s], v.x);
        atomicAdd(&d_q[b * HSc + (2 * p + 1) * Sc + s], v.y);
    }
}

// ---------------- K2: u[b][e] = sum_d (q[b][d]*zinv_last) * A[d][e] --------
// grid (4 e-chunks, 32 d-chunks of 32), block 256. Batch-32 A loads.
__global__ void __launch_bounds__(256) k_u(const float* __restrict__ A) {
    int ebase = blockIdx.x * 256;
    int dbase = blockIdx.y * 32;
    int t = threadIdx.x;
    __shared__ __align__(16) float sq[32 * 8];   // sq[dd][b]
    {
        int dd = t >> 3, b = t & 7;
        int d = dbase + dd;
        sq[t] = d_q[b * HSc + d] * d_zinv[(Lc - 1) * Hc + (d >> 7)];
    }
    __syncthreads();

    int e = ebase + t;
    unsigned long long a2[4] = {};
    const float* Ap = A + (size_t)dbase * HSc + e;
    float av[32];
    #pragma unroll
    for (int k = 0; k < 32; k++) av[k] = Ap[k * HSc];
    #pragma unroll
    for (int k = 0; k < 32; k++) {
        unsigned long long ad = pack2(av[k]);
        ulonglong2 q01 = *(const ulonglong2*)&sq[k * 8];
        ulonglong2 q23 = *(const ulonglong2*)&sq[k * 8 + 4];
        fma2(a2[0], ad, q01.x);
        fma2(a2[1], ad, q01.y);
        fma2(a2[2], ad, q23.x);
        fma2(a2[3], ad, q23.y);
    }
    #pragma unroll
    for (int p = 0; p < 4; p++) {
        float2 v = unpack2(a2[p]);
        atomicAdd(&d_u[(2 * p) * HSc + e], v.x);
        atomicAdd(&d_u[(2 * p + 1) * HSc + e], v.y);
    }
}

// ---------------- K3: G2[h][j][b] += sum_{s quarter} u[b][h*S+s]*x[b][j][s] -
// s-split x4: grid (L/64, 4, B) = 1024 blocks, block 256. smem 18.4KB.
__global__ void __launch_bounds__(256) k_G(const float* __restrict__ x) {
    int b = blockIdx.z;
    int sz = blockIdx.y;                 // s-quarter: 0..3
    int jbase = blockIdx.x * 64;
    int t = threadIdx.x, w = t >> 5, lane = t & 31;
    __shared__ __align__(16) char sbuf[16384];                   // spart overlays sxT
    __shared__ __align__(16) unsigned long long su2[8 * 32];     // 2048 B
    float* sxT = (float*)sbuf;                                   // sxT[sl][j], pitch 66 (8448 B)
    unsigned long long (*spart)[32][8] =
        (unsigned long long (*)[32][8])sbuf;                     // [warp][jp][h] 16384 B

    int s0 = sz * 32;

    // stage x transposed: batch-8 explicit loads (64 j x 32 s), then STS
    int sl = t & 31, jh = t >> 5;        // jh in [0,8)
    float xv[8];
    {
        const float* xb = x + ((size_t)b * Lc + jbase) * Sc + s0 + sl;
        #pragma unroll
        for (int r = 0; r < 8; r++) xv[r] = xb[(size_t)(r * 8 + jh) * Sc];
    }
    {
        int h = t >> 5, sll = t & 31;
        su2[h * 32 + sll] = pack2(d_u[b * HSc + h * Sc + s0 + sll]);
    }
    #pragma unroll
    for (int r = 0; r < 8; r++) sxT[sl * 66 + r * 8 + jh] = xv[r];
    __syncthreads();

    // compute: warp w covers sl in [4w, 4w+4); lane = j-pair
    unsigned long long acc[8] = {};
    int sc0 = w * 4;
    #pragma unroll
    for (int si = 0; si < 4; si++) {
        int slc = sc0 + si;
        unsigned long long xvv = *(const unsigned long long*)&sxT[slc * 66 + 2 * lane];
        #pragma unroll
        for (int h = 0; h < 8; h++)
            fma2(acc[h], xvv, su2[h * 32 + slc]);
    }
    __syncthreads();   // sxT reads done before spart overwrites buffer

    #pragma unroll
    for (int h = 0; h < 8; h++) spart[w][lane][h] = acc[h];
    __syncthreads();

    {
        int jp = t >> 3, h = t & 7;
        float vx = 0.f, vy = 0.f;
        #pragma unroll
        for (int c = 0; c < 8; c++) {
            float2 p = unpack2(spart[c][jp][h]);
            vx += p.x; vy += p.y;
        }
        float* gp = d_G + (size_t)h * (Lc * Bc) + (jbase + 2 * jp) * 8 + b;
        atomicAdd(gp,     vx);
        atomicAdd(gp + 8, vy);
    }
}

// ---------------- K4: Toeplitz causal correlation (dominant) ---------------
// jg granularity 2; heavy-first block order packs the tail wave.
__global__ void __launch_bounds__(128) k_scores() {
    int lt = (int)gridDim.x - 1 - (int)blockIdx.x;
    int jg = blockIdx.y, h = blockIdx.z;
    int jt0 = jg * 2;
    if (jt0 > lt) return;
    int jt1 = min(jt0 + 2, lt + 1);
    int lbase = lt * 128;
    int t = threadIdx.x, w = t >> 5, lane = t & 31;

    unsigned long long acc[4][4] = {};   // [k][b-pair]
    const float* eTh = d_eT + (size_t)h * Lc;
    const float* Gh  = d_G + (size_t)h * Lc * Bc;

    __shared__ __align__(16) float se[256];

    for (int jt = jt0; jt < jt1; jt++) {
        int D0 = lbase - jt * 128;          // >= 0
        __syncthreads();
        {
            int d0 = D0 - 127 + t, d1 = D0 + 1 + t;
            se[t] = (d0 >= 0) ? eTh[d0] : 0.f;
            se[t + 128] = (d1 >= 0) ? eTh[d1] : 0.f;
        }
        __syncthreads();

        int jb = jt * 128 + w * 32;
        int base_idx = 127 + lane - w * 32;
        #pragma unroll 2
        for (int jj = 0; jj < 32; jj++) {
            int j = jb + jj;
            ulonglong2 g01 = *(const ulonglong2*)(Gh + j * 8);
            ulonglong2 g23 = *(const ulonglong2*)(Gh + j * 8 + 4);
            int bi = base_idx - jj;
            #pragma unroll
            for (int k = 0; k < 4; k++) {
                unsigned long long ev = pack2(se[bi + 32 * k]);
                fma2(acc[k][0], ev, g01.x);
                fma2(acc[k][1], ev, g01.y);
                fma2(acc[k][2], ev, g23.x);
                fma2(acc[k][3], ev, g23.y);
            }
        }
    }

    __shared__ __align__(16) float sacc[4][128][8];
    #pragma unroll
    for (int k = 0; k < 4; k++) {
        float2 p0 = unpack2(acc[k][0]);
        float2 p1 = unpack2(acc[k][1]);
        float2 p2 = unpack2(acc[k][2]);
        float2 p3 = unpack2(acc[k][3]);
        *(float4*)&sacc[w][lane + 32 * k][0] = make_float4(p0.x, p0.y, p1.x, p1.y);
        *(float4*)&sacc[w][lane + 32 * k][4] = make_float4(p2.x, p2.y, p3.x, p3.y);
    }
    __syncthreads();

    int l = lbase + t;
    if (l < Lc - 1) {
        float zi = d_zinv[l * Hc + h];
        #pragma unroll
        for (int b = 0; b < 8; b++) {
            float v = sacc[0][t][b] + sacc[1][t][b] + sacc[2][t][b] + sacc[3][t][b];
            atomicAdd(&d_scores[b * Lc + l], v * zi);
        }
    }
}

// ---------------- K5: fused softmax stats + out ------------------------------
// grid (L/64, B), block 128. Batch-32 loads.
__global__ void __launch_bounds__(128) k_out(const float* __restrict__ x,
                                             float* __restrict__ out) {
    int lbase = blockIdx.x * 64;
    int b = blockIdx.y;
    int t = threadIdx.x;
    const float* sc = d_scores + b * Lc;

    __shared__ float red[128];
    float m = -1e30f;
    for (int l = t; l < Lc - 1; l += 128) m = fmaxf(m, sc[l]);
    red[t] = m; __syncthreads();
    for (int o = 64; o > 0; o >>= 1) {
        if (t < o) red[t] = fmaxf(red[t], red[t + o]);
        __syncthreads();
    }
    float M = red[0]; __syncthreads();
    float ss = 0.f;
    for (int l = t; l < Lc - 1; l += 128) ss += expf(sc[l] - M);
    red[t] = ss; __syncthreads();
    for (int o = 64; o > 0; o >>= 1) {
        if (t < o) red[t] += red[t + o];
        __syncthreads();
    }
    float sinv = 1.f / red[0];
    __syncthreads();

    __shared__ float wsm[64];
    if (t < 64) {
        int lg = lbase + t;
        wsm[t] = (lg < Lc - 1) ? expf(sc[lg] - M) * sinv : 0.f;
    }
    __syncthreads();

    float acc = 0.f;
    const float* xp = x + ((size_t)b * Lc + lbase) * Sc + t;
    #pragma unroll
    for (int j0 = 0; j0 < 64; j0 += 32) {
        float xv[32];
        #pragma unroll
        for (int k = 0; k < 32; k++) xv[k] = xp[(j0 + k) * Sc];
        #pragma unroll
        for (int k = 0; k < 32; k++) acc += wsm[j0 + k] * xv[k];
    }
    atomicAdd(&out[b * Sc + t], acc);
}

// ---------------- launch ----------------------------------------------------
extern "C" void kernel_launch(void* const* d_in, const int* in_sizes, int n_in,
                              void* d_out, int out_size) {
    const float *x = nullptr, *W = nullptr, *A = nullptr;
    for (int i = 0; i < n_in; i++) {
        if (in_sizes[i] == Bc * Lc * Sc)      x = (const float*)d_in[i];
        else if (in_sizes[i] == Lc * Hc)      W = (const float*)d_in[i];
        else if (in_sizes[i] == HSc * HSc)    A = (const float*)d_in[i];
    }
    float* out = (float*)d_out;

    k_init<<<24, 1024>>>(W, out);
    k_q<<<dim3(Lc / 32, Bc), 128>>>(x);
    k_u<<<dim3(HSc / 256, 32), 256>>>(A);
    k_G<<<dim3(Lc / 64, 4, Bc), 256>>>(x);
    k_scores<<<dim3(Lc / 128, 8, Hc), 128>>>();
    k_out<<<dim3(Lc / 64, Bc), 128>>>(x, out);
}